// round 13
// baseline (speedup 1.0000x reference)
#include <cuda_runtime.h>
#include <math_constants.h>
#include <cstddef>

#define B_   16
#define N_   4096
#define S_   1024
#define K_   32
#define CF_  64
#define WAVES 64

// device scratch (no allocation allowed; zero-initialized at module load)
__device__ int   g_knn[B_ * S_ * K_];
__device__ float g_fW0[B_ * N_ * 64];     // feat @ W0[3:67]  (16 MB)
__device__ float g_nxyz[B_ * S_ * 3];     // centroid scratch (never poisoned)
__device__ int   g_flag[B_ * S_ / 16];    // fps progress   [b*64 + w]
__device__ int   g_kdone[B_ * S_ / 16];   // knn done       [b*64 + w]
__device__ int   g_pflag[256];            // pre done       [pb]

// ---------------------------------------------------------------- helpers
__device__ __forceinline__ unsigned long long pack2(float a) {
    unsigned long long r;
    asm("mov.b64 %0, {%1, %1};" : "=l"(r) : "f"(a));
    return r;
}
__device__ __forceinline__ void fma2(unsigned long long& d,
                                     unsigned long long a, unsigned long long b) {
    asm("fma.rn.f32x2 %0, %1, %2, %0;" : "+l"(d) : "l"(a), "l"(b));
}
__device__ __forceinline__ float2 unpack2(unsigned long long v) {
    float2 f;
    asm("mov.b64 {%0, %1}, %2;" : "=f"(f.x), "=f"(f.y) : "l"(v));
    return f;
}
__device__ __forceinline__ int ld_acq(const int* p) {
    int v;
    asm volatile("ld.acquire.gpu.global.b32 %0, [%1];" : "=r"(v) : "l"(p) : "memory");
    return v;
}
__device__ __forceinline__ void st_rel(int* p, int v) {
    asm volatile("st.release.gpu.global.b32 [%0], %1;" :: "l"(p), "r"(v) : "memory");
}

// ============================================================================
// 0) clear_flags — runs before mega_kernel every launch (kernel-boundary
//    ordering makes every replay re-synchronize exactly like the first run)
// ============================================================================
__global__ void clear_flags()
{
    const int t = blockIdx.x * blockDim.x + threadIdx.x;
    if (t < B_ * S_ / 16) { g_flag[t] = 0; g_kdone[t] = 0; }
    if (t < 256) g_pflag[t] = 0;
}

// ============================================================================
// FPS body — 256 threads, 16 pts/thread. Bit-correct vs reference.
// ============================================================================
__device__ void fps_body(int b, float* sm, const float* __restrict__ xyz,
                         float* __restrict__ newxyz)
{
    float* sx = sm;
    float* sy = sm + N_;
    float* sz = sm + 2 * N_;
    __shared__ unsigned fpv[2][8];
    __shared__ int      fpi[2][8];

    const int t = threadIdx.x;
    const int lane = t & 31, warp = t >> 5;
    const float* base = xyz + (size_t)b * N_ * 3;

    float px[16], py[16], pz[16], dd[16];
#pragma unroll
    for (int j = 0; j < 16; j++) {
        int p = t + j * 256;
        float x = base[3 * p + 0], y = base[3 * p + 1], z = base[3 * p + 2];
        px[j] = x; py[j] = y; pz[j] = z;
        sx[p] = x; sy[p] = y; sz[p] = z;
        dd[j] = 1e10f;
    }
    __syncthreads();

    int far = 0;
    for (int it = 0; it < S_; it++) {
        const int pr = it & 1;
        const float cx = sx[far], cy = sy[far], cz = sz[far];

        unsigned bu = 0u;
        int      bi = 0x7fffffff;
#pragma unroll
        for (int j = 0; j < 16; j++) {
            float dx = __fsub_rn(px[j], cx);
            float dy = __fsub_rn(py[j], cy);
            float dz = __fsub_rn(pz[j], cz);
            float d2 = __fadd_rn(__fadd_rn(__fmul_rn(dx, dx), __fmul_rn(dy, dy)),
                                 __fmul_rn(dz, dz));
            float nd = fminf(dd[j], d2);
            dd[j] = nd;
            unsigned u = __float_as_uint(nd);   // nd >= 0 -> monotonic bits
            if (u > bu) { bu = u; bi = t + j * 256; }  // ascending idx -> first max
        }
        unsigned rv = __reduce_max_sync(0xffffffffu, bu);
        int      ri = __reduce_min_sync(0xffffffffu, (bu == rv) ? bi : 0x7fffffff);
        if (lane == 0) { fpv[pr][warp] = rv; fpi[pr][warp] = ri; }
        __syncthreads();

        unsigned v  = (lane < 8) ? fpv[pr][lane] : 0u;
        int      ii = (lane < 8) ? fpi[pr][lane] : 0x7fffffff;
        unsigned mv = __reduce_max_sync(0xffffffffu, v);
        far         = __reduce_min_sync(0xffffffffu, (v == mv) ? ii : 0x7fffffff);

        if (t == 0) {
            const size_t o = (size_t)(b * S_ + it) * 3;
            float x = sx[far], y = sy[far], z = sz[far];
            newxyz[o + 0] = x; newxyz[o + 1] = y; newxyz[o + 2] = z;
            g_nxyz[o + 0] = x; g_nxyz[o + 1] = y; g_nxyz[o + 2] = z;
            if ((it & 15) == 15)
                st_rel(&g_flag[(b * S_ + it) >> 4], 1);
        }
    }
}

// ============================================================================
// PRE body — 256 threads, 256 points: g_fW0 = feat @ W0[3:67], 8x8 tiles
// ============================================================================
__device__ void pre_body(int pb, float* sm, const float* __restrict__ feat,
                         const float* __restrict__ W0)
{
    float* Wf = sm;            // 4096
    float* R  = sm + 4096;     // 256*68
    const int t = threadIdx.x;
    const int base = pb * 256;

    for (int i = t; i < 4096; i += 256) Wf[i] = W0[192 + i];
    {
        const float4* fr = (const float4*)(feat + (size_t)(base + t) * 64);
        float* dst = R + t * 68;
#pragma unroll
        for (int j = 0; j < 16; j++) {
            float4 v = fr[j];
            dst[4 * j + 0] = v.x; dst[4 * j + 1] = v.y;
            dst[4 * j + 2] = v.z; dst[4 * j + 3] = v.w;
        }
    }
    __syncthreads();

    const int rg = t >> 3, cg = t & 7;
    const int r0 = rg * 8, co = cg * 8;

    unsigned long long acc[8][4];
#pragma unroll
    for (int i = 0; i < 8; i++)
#pragma unroll
        for (int p = 0; p < 4; p++) acc[i][p] = 0;

#pragma unroll 2
    for (int ci = 0; ci < 64; ci++) {
        const ulonglong2* wr = (const ulonglong2*)(Wf + ci * 64 + co);
        ulonglong2 w0 = wr[0], w1 = wr[1];
#pragma unroll
        for (int i = 0; i < 8; i++) {
            unsigned long long a = pack2(R[(r0 + i) * 68 + ci]);
            fma2(acc[i][0], a, w0.x);
            fma2(acc[i][1], a, w0.y);
            fma2(acc[i][2], a, w1.x);
            fma2(acc[i][3], a, w1.y);
        }
    }
#pragma unroll
    for (int i = 0; i < 8; i++) {
        float2* o = (float2*)(g_fW0 + (size_t)(base + r0 + i) * 64 + co);
#pragma unroll
        for (int p = 0; p < 4; p++) o[p] = unpack2(acc[i][p]);
    }
    __syncthreads();
    if (t == 0) st_rel(&g_pflag[pb], 1);
}

// ============================================================================
// KNN body — 256 threads, 16 queries (batch b, wave w); gated on fps flag.
// ============================================================================
__device__ __forceinline__ void scan_select(const unsigned* hist, unsigned NEED,
                                            unsigned* out_c, unsigned* out_r, int t)
{
    if (t < 32) {
        unsigned acc[8]; unsigned tl = 0;
#pragma unroll
        for (int j = 0; j < 8; j++) { acc[j] = hist[t * 8 + j]; tl += acc[j]; }
        unsigned run = tl;
#pragma unroll
        for (int off = 1; off < 32; off <<= 1) {
            unsigned n = __shfl_up_sync(0xffffffffu, run, off);
            if (t >= off) run += n;
        }
        unsigned excl = run - tl;
        if (excl < NEED && NEED <= run) {
            unsigned c = excl;
#pragma unroll
            for (int j = 0; j < 8; j++) {
                if (c + acc[j] >= NEED) { *out_c = t * 8 + j; *out_r = NEED - c; break; }
                c += acc[j];
            }
        }
    }
}

#define NCAND 256

__device__ void knn_body(int w, int b, float* sm, const float* __restrict__ xyz)
{
    float*    sx   = sm;
    float*    sy   = sm + N_;
    float*    sz   = sm + 2 * N_;
    unsigned* du   = (unsigned*)(sm + 3 * N_);
    unsigned* hist = du + N_;
    unsigned long long* cand = (unsigned long long*)(hist + 256);
    __shared__ unsigned s_c1, s_need1, s_c2, s_need2, s_cnt, s_ccnt;

    const int t = threadIdx.x;
    const int qbase = b * S_ + 16 * w;

    const float* bp = xyz + (size_t)b * N_ * 3;
    for (int i = t; i < N_ * 3; i += 256) {
        float v = bp[i];
        int p = i / 3, c = i - 3 * p;
        (c == 0 ? sx : (c == 1 ? sy : sz))[p] = v;
    }

    if (t == 0) {
        while (ld_acq(&g_flag[b * 64 + w]) == 0) __nanosleep(128);
    }
    __syncthreads();

    for (int q = 0; q < 16; q++) {
        const int row = qbase + q;
        const float qx = g_nxyz[row * 3 + 0];
        const float qy = g_nxyz[row * 3 + 1];
        const float qz = g_nxyz[row * 3 + 2];
        const float a2 = __fadd_rn(__fadd_rn(__fmul_rn(qx, qx), __fmul_rn(qy, qy)),
                                   __fmul_rn(qz, qz));

        hist[t] = 0;
        if (t == 0) { s_cnt = 0; s_ccnt = 0; }
        __syncthreads();

        for (int i = t; i < N_; i += 256) {
            float x = sx[i], y = sy[i], z = sz[i];
            float b2 = __fadd_rn(__fadd_rn(__fmul_rn(x, x), __fmul_rn(y, y)),
                                 __fmul_rn(z, z));
            float ab = __fadd_rn(__fadd_rn(__fmul_rn(qx, x), __fmul_rn(qy, y)),
                                 __fmul_rn(qz, z));
            float d2 = fmaxf(__fadd_rn(__fsub_rn(a2, __fmul_rn(2.0f, ab)), b2), 0.0f);
            unsigned u = __float_as_uint(d2);
            du[i] = u;
            atomicAdd(&hist[u >> 24], 1u);
        }
        __syncthreads();

        scan_select(hist, K_, &s_c1, &s_need1, t);
        __syncthreads();
        const unsigned c1 = s_c1, need1 = s_need1;

        hist[t] = 0;
        __syncthreads();
        for (int i = t; i < N_; i += 256) {
            unsigned u = du[i];
            if ((u >> 24) == c1) atomicAdd(&hist[(u >> 16) & 255u], 1u);
        }
        __syncthreads();

        scan_select(hist, need1, &s_c2, &s_need2, t);
        __syncthreads();
        const unsigned thr16 = (c1 << 8) | s_c2;
        const unsigned need2 = s_need2;

        for (int i = t; i < N_; i += 256) {
            unsigned u = du[i];
            unsigned k16 = u >> 16;
            if (k16 < thr16) {
                unsigned p = atomicAdd(&s_cnt, 1u);
                g_knn[(size_t)row * K_ + p] = i;
            } else if (k16 == thr16) {
                unsigned c = atomicAdd(&s_ccnt, 1u);
                if (c < NCAND) cand[c] = (((unsigned long long)u) << 12) | (unsigned)i;
            }
        }
        __syncthreads();

        if (t == 0) {
            int baseo = (int)s_cnt;
            int nc = (int)(s_ccnt < (unsigned)NCAND ? s_ccnt : (unsigned)NCAND);
            for (int j = 0; j < (int)need2; j++) {
                unsigned long long best = ~0ULL; int bj = 0;
                for (int m = 0; m < nc; m++)
                    if (cand[m] < best) { best = cand[m]; bj = m; }
                g_knn[(size_t)row * K_ + baseo + j] = (int)(best & 0xFFFu);
                cand[bj] = ~0ULL;
            }
        }
        __syncthreads();
    }

    if (t == 0) st_rel(&g_kdone[b * 64 + w], 1);
}

// ============================================================================
// MLP body — 256 threads, 8 segments (rows seg0..seg0+7); gated on knn + pre.
// R11 crossbar-optimized 8x8-tile GEMMs, in-place X1, shfl pool.
// ============================================================================
#define RST 72
// dynamic smem (floats):
//  AsX1 0..18432 | W1s 18432..22528 | W2s 22528..26624 | W0s 26624..26816 |
//  bn0 26816 | bn1 27008 | bn2 27200..27584 | gxs 27584..28352
#define MEGA_SMEM_FL 28352

__device__ void mlp_body(int w, int m, float* sm,
    const float* __restrict__ xyz, const float* __restrict__ fW0,
    const float* __restrict__ W0, const float* __restrict__ b0,
    const float* __restrict__ g0, const float* __restrict__ be0,
    const float* __restrict__ m0, const float* __restrict__ v0,
    const float* __restrict__ W1, const float* __restrict__ b1,
    const float* __restrict__ g1, const float* __restrict__ be1,
    const float* __restrict__ m1, const float* __restrict__ v1,
    const float* __restrict__ W2, const float* __restrict__ b2,
    const float* __restrict__ g2, const float* __restrict__ be2,
    const float* __restrict__ m2, const float* __restrict__ v2,
    float* __restrict__ outp)
{
    float* AsX1 = sm;
    float* W1s  = sm + 18432;
    float* W2s  = sm + 22528;
    float* W0s  = sm + 26624;
    float* bn0  = sm + 26816;
    float* bn1  = sm + 27008;
    float* bn2  = sm + 27200;
    float* gxs  = sm + 27584;
    __shared__ int   sidx[256];
    __shared__ float qv[24];

    const int t = threadIdx.x;
    const int bb = m >> 1;
    const int seg0 = bb * S_ + 16 * w + 8 * (m & 1);
    const size_t row0 = (size_t)seg0 * 32;

    // ---- stage weights / constants (W1 swizzled; W2 first half swizzled) ----
    for (int i = t; i < 4096; i += 256) {
        const int ci = i >> 6, col = i & 63;
        const int cgx = col >> 3, kk = col & 7;
        W1s[ci * 64 + (kk >> 2) * 32 + cgx * 4 + (kk & 3)] = W1[i];
        W2s[ci * 64 + (kk >> 2) * 32 + cgx * 4 + (kk & 3)] = W2[ci * 128 + col];
    }
    if (t < 192) W0s[t] = W0[t];
    if (t < 64) {
        float s0 = g0[t] * rsqrtf(v0[t] + 1e-3f);
        bn0[t] = s0; bn0[64 + t] = be0[t] - m0[t] * s0; bn0[128 + t] = b0[t];
        float s1 = g1[t] * rsqrtf(v1[t] + 1e-3f);
        bn1[t] = s1; bn1[64 + t] = be1[t] - m1[t] * s1; bn1[128 + t] = b1[t];
    }
    if (t < 128) {
        float s2 = g2[t] * rsqrtf(v2[t] + 1e-3f);
        bn2[t] = s2; bn2[128 + t] = be2[t] - m2[t] * s2; bn2[256 + t] = b2[t];
    }

    // ---- gate on knn + pre (overlaps with weight staging above) ----
    if (t == 0) {
        while (ld_acq(&g_kdone[bb * 64 + w]) == 0) __nanosleep(128);
#pragma unroll 1
        for (int i = 0; i < 16; i++)
            while (ld_acq(&g_pflag[bb * 16 + i]) == 0) __nanosleep(128);
    }
    __syncthreads();

    sidx[t] = g_knn[row0 + t];
    if (t < 24) qv[t] = g_nxyz[seg0 * 3 + t];
    __syncthreads();

    // ---- gather: one thread per row ----
    {
        const int r = t;
        const int seg = r >> 5;
        const int id = sidx[r];
        const float4* fr = (const float4*)(fW0 + ((size_t)bb * N_ + id) * 64);
        float* dst = AsX1 + r * RST;
#pragma unroll
        for (int j = 0; j < 16; j++) {
            float4 v = fr[j];
            dst[4 * j + 0] = v.x; dst[4 * j + 1] = v.y;
            dst[4 * j + 2] = v.z; dst[4 * j + 3] = v.w;
        }
        const float* xr = xyz + ((size_t)bb * N_ + id) * 3;
        gxs[r * 3 + 0] = __fsub_rn(xr[0], qv[seg * 3 + 0]);
        gxs[r * 3 + 1] = __fsub_rn(xr[1], qv[seg * 3 + 1]);
        gxs[r * 3 + 2] = __fsub_rn(xr[2], qv[seg * 3 + 2]);
    }
    __syncthreads();

    // ---- layer-0 transform in smem ----
    for (int i = t; i < 256 * 64; i += 256) {
        const int r = i >> 6, c = i & 63;
        float v = AsX1[r * RST + c];
        v += gxs[r * 3 + 0] * W0s[c];
        v += gxs[r * 3 + 1] * W0s[64 + c];
        v += gxs[r * 3 + 2] * W0s[128 + c];
        v = fmaxf(v + bn0[128 + c], 0.0f);
        AsX1[r * RST + c] = v * bn0[c] + bn0[64 + c];
    }
    __syncthreads();

    const int wp   = t >> 5;           // warp = segment within block
    const int lane = t & 31;
    const int k    = lane >> 3;        // rgroup-in-warp 0..3
    const int cg   = lane & 7;
    const int co   = cg * 8;
    const int cg4  = cg * 4;
    const float* arow = AsX1 + (32 * wp + k) * RST;   // rows 32wp+k+4i

    // ---- GEMM1: 256x64, 8x8 per thread; in-place ----
    {
        unsigned long long acc[8][4];
#pragma unroll
        for (int i = 0; i < 8; i++)
#pragma unroll
            for (int p = 0; p < 4; p++) acc[i][p] = 0;

#pragma unroll 2
        for (int ci2 = 0; ci2 < 32; ci2++) {
            const int ci = 2 * ci2;
            const float* wpp = W1s + ci * 64;
            ulonglong2 u00 = *(const ulonglong2*)(wpp + cg4);
            ulonglong2 u01 = *(const ulonglong2*)(wpp + 32 + cg4);
            ulonglong2 u10 = *(const ulonglong2*)(wpp + 64 + cg4);
            ulonglong2 u11 = *(const ulonglong2*)(wpp + 96 + cg4);
#pragma unroll
            for (int i = 0; i < 8; i++) {
                float2 a = *(const float2*)(arow + i * 4 * RST + ci);
                unsigned long long a0 = pack2(a.x);
                unsigned long long a1 = pack2(a.y);
                fma2(acc[i][0], a0, u00.x); fma2(acc[i][1], a0, u00.y);
                fma2(acc[i][2], a0, u01.x); fma2(acc[i][3], a0, u01.y);
                fma2(acc[i][0], a1, u10.x); fma2(acc[i][1], a1, u10.y);
                fma2(acc[i][2], a1, u11.x); fma2(acc[i][3], a1, u11.y);
            }
        }
        __syncthreads();

#pragma unroll
        for (int i = 0; i < 8; i++) {
            float* o = AsX1 + (32 * wp + k + 4 * i) * RST + co;
#pragma unroll
            for (int p = 0; p < 4; p++) {
                float2 v = unpack2(acc[i][p]);
                int ca = co + 2 * p, cb = ca + 1;
                float2 r2;
                r2.x = fmaxf(v.x + bn1[128 + ca], 0.0f) * bn1[ca] + bn1[64 + ca];
                r2.y = fmaxf(v.y + bn1[128 + cb], 0.0f) * bn1[cb] + bn1[64 + cb];
                *(float2*)(o + 2 * p) = r2;
            }
        }
    }
    __syncthreads();

    // ---- GEMM2: two 64-col passes (W2 re-staged), shfl pool ----
#pragma unroll 1
    for (int ph = 0; ph < 2; ph++) {
        if (ph == 1) {
            __syncthreads();
            for (int i = t; i < 4096; i += 256) {
                const int ci = i >> 6, col = i & 63;
                const int cgx = col >> 3, kk = col & 7;
                W2s[ci * 64 + (kk >> 2) * 32 + cgx * 4 + (kk & 3)] = W2[ci * 128 + 64 + col];
            }
            __syncthreads();
        }

        unsigned long long acc[8][4];
#pragma unroll
        for (int i = 0; i < 8; i++)
#pragma unroll
            for (int p = 0; p < 4; p++) acc[i][p] = 0;

#pragma unroll 2
        for (int ci2 = 0; ci2 < 32; ci2++) {
            const int ci = 2 * ci2;
            const float* wpp = W2s + ci * 64;
            ulonglong2 u00 = *(const ulonglong2*)(wpp + cg4);
            ulonglong2 u01 = *(const ulonglong2*)(wpp + 32 + cg4);
            ulonglong2 u10 = *(const ulonglong2*)(wpp + 64 + cg4);
            ulonglong2 u11 = *(const ulonglong2*)(wpp + 96 + cg4);
#pragma unroll
            for (int i = 0; i < 8; i++) {
                float2 a = *(const float2*)(arow + i * 4 * RST + ci);
                unsigned long long a0 = pack2(a.x);
                unsigned long long a1 = pack2(a.y);
                fma2(acc[i][0], a0, u00.x); fma2(acc[i][1], a0, u00.y);
                fma2(acc[i][2], a0, u01.x); fma2(acc[i][3], a0, u01.y);
                fma2(acc[i][0], a1, u10.x); fma2(acc[i][1], a1, u10.y);
                fma2(acc[i][2], a1, u11.x); fma2(acc[i][3], a1, u11.y);
            }
        }

        const int gco = ph * 64 + co;
        float pm[8];
#pragma unroll
        for (int j = 0; j < 8; j++) pm[j] = -CUDART_INF_F;
#pragma unroll
        for (int i = 0; i < 8; i++) {
#pragma unroll
            for (int p = 0; p < 4; p++) {
                float2 v = unpack2(acc[i][p]);
                int ca = gco + 2 * p, cb = ca + 1;
                float oa = fmaxf(v.x + bn2[256 + ca], 0.0f) * bn2[ca] + bn2[128 + ca];
                float ob = fmaxf(v.y + bn2[256 + cb], 0.0f) * bn2[cb] + bn2[128 + cb];
                pm[2 * p]     = fmaxf(pm[2 * p], oa);
                pm[2 * p + 1] = fmaxf(pm[2 * p + 1], ob);
            }
        }
#pragma unroll
        for (int j = 0; j < 8; j++) {
            pm[j] = fmaxf(pm[j], __shfl_xor_sync(0xffffffffu, pm[j], 8));
            pm[j] = fmaxf(pm[j], __shfl_xor_sync(0xffffffffu, pm[j], 16));
        }
        if (lane < 8) {
            float* o = outp + (size_t)(seg0 + wp) * 128 + gco;
#pragma unroll
            for (int j = 0; j < 8; j++) o[j] = pm[j];
        }
    }
}

// ============================================================================
// MEGA kernel: [0,16) fps | [16,272) pre | 64 waves x (16 knn + 32 mlp)
// ============================================================================
__global__ void __launch_bounds__(256, 2) mega_kernel(
    const float* __restrict__ xyz, const float* __restrict__ feat,
    const float* __restrict__ fW0,
    const float* __restrict__ W0, const float* __restrict__ b0,
    const float* __restrict__ g0, const float* __restrict__ be0,
    const float* __restrict__ m0, const float* __restrict__ v0,
    const float* __restrict__ W1, const float* __restrict__ b1,
    const float* __restrict__ g1, const float* __restrict__ be1,
    const float* __restrict__ m1, const float* __restrict__ v1,
    const float* __restrict__ W2, const float* __restrict__ b2,
    const float* __restrict__ g2, const float* __restrict__ be2,
    const float* __restrict__ m2, const float* __restrict__ v2,
    float* __restrict__ newxyz, float* __restrict__ pooled)
{
    extern __shared__ float sm[];
    const int bid = blockIdx.x;
    if (bid < 16) {
        fps_body(bid, sm, xyz, newxyz);
    } else if (bid < 272) {
        pre_body(bid - 16, sm, feat, W0);
    } else {
        const int x = bid - 272;
        const int w = x / 48;
        const int r = x - 48 * w;
        if (r < 16) knn_body(w, r, sm, xyz);
        else        mlp_body(w, r - 16, sm, xyz, fW0,
                             W0, b0, g0, be0, m0, v0,
                             W1, b1, g1, be1, m1, v1,
                             W2, b2, g2, be2, m2, v2, pooled);
    }
}

// ============================================================================
extern "C" void kernel_launch(void* const* d_in, const int* in_sizes, int n_in,
                              void* d_out, int out_size)
{
    (void)in_sizes; (void)n_in; (void)out_size;
    const float* xyz  = (const float*)d_in[0];
    const float* feat = (const float*)d_in[1];
    const float* P[18];
    for (int i = 0; i < 18; i++) P[i] = (const float*)d_in[2 + i];

    float* out    = (float*)d_out;
    float* newxyz = out;
    float* pooled = out + (size_t)B_ * S_ * 3;

    float* fW0;  cudaGetSymbolAddress((void**)&fW0, g_fW0);

    const int smem = MEGA_SMEM_FL * 4;   // 113408
    cudaFuncSetAttribute(mega_kernel, cudaFuncAttributeMaxDynamicSharedMemorySize, smem);

    clear_flags<<<4, 256>>>();           // flags -> 0 before every replay

    const int grid = 272 + WAVES * 48;   // 3344
    mega_kernel<<<grid, 256, smem>>>(
        xyz, feat, fW0,
        P[0],  P[1],  P[2],  P[3],  P[4],  P[5],
        P[6],  P[7],  P[8],  P[9],  P[10], P[11],
        P[12], P[13], P[14], P[15], P[16], P[17],
        newxyz, pooled);
}